// round 15
// baseline (speedup 1.0000x reference)
#include <cuda_runtime.h>
#include <cuda_fp16.h>

#define HW    512
#define IMG   (HW*HW)
#define BATCH 32
#define NTOT  (BATCH*IMG)        // per stream
#define NWARP 4096               // 64 images * 64 stripes of 8 rows
#define FULLM 0xffffffffu

// __device__ scratch (no allocation allowed)
__device__ __align__(16) __half g_h0[2*NTOT];   // image i = s*32+b
__device__ __align__(16) __half g_eA[2*NTOT];
__device__ __align__(16) __half g_eB[2*NTOT];
__device__ __align__(16) __half g_P [2*NTOT];   // running product (1-skel), fp16
__device__ double g_part[NWARP*2];

__device__ __forceinline__ int clampi(int v){ return v<0?0:(v>HW-1?HW-1:v); }

struct Row { __half2 h[8]; };    // 16 halves: lane covers gx [16*lane, 16*lane+15]

__device__ __forceinline__ unsigned h2u(__half2 x){ return *reinterpret_cast<unsigned*>(&x); }
__device__ __forceinline__ __half2  u2h(unsigned x){ return *reinterpret_cast<__half2*>(&x); }

__device__ __forceinline__ Row ld_row(const __half* base, int y, int xoff){
    const uint4* p = reinterpret_cast<const uint4*>(base + (size_t)clampi(y)*HW + xoff);
    uint4 a = p[0], b = p[1];
    Row r;
    r.h[0]=u2h(a.x); r.h[1]=u2h(a.y); r.h[2]=u2h(a.z); r.h[3]=u2h(a.w);
    r.h[4]=u2h(b.x); r.h[5]=u2h(b.y); r.h[6]=u2h(b.z); r.h[7]=u2h(b.w);
    return r;
}
__device__ __forceinline__ void st_row(__half* base, int y, int xoff, const Row& r){
    uint4 a, b;
    a.x=h2u(r.h[0]); a.y=h2u(r.h[1]); a.z=h2u(r.h[2]); a.w=h2u(r.h[3]);
    b.x=h2u(r.h[4]); b.y=h2u(r.h[5]); b.z=h2u(r.h[6]); b.w=h2u(r.h[7]);
    uint4* p = reinterpret_cast<uint4*>(base + (size_t)y*HW + xoff);
    p[0]=a; p[1]=b;
}

// horizontal 3-min over the 512-wide row; lane-boundary halves via shuffle;
// image x-edges use duplicated edge element (== SAME pad identity for min).
__device__ __forceinline__ Row hmin3_row(const Row& m, int lane){
    unsigned up = __shfl_up_sync(FULLM, h2u(m.h[7]), 1);
    unsigned dn = __shfl_down_sync(FULLM, h2u(m.h[0]), 1);
    __half L = (lane==0)  ? __low2half(m.h[0])  : __high2half(u2h(up));
    __half R = (lane==31) ? __high2half(m.h[7]) : __low2half(u2h(dn));
    Row o;
    #pragma unroll
    for (int i=0;i<8;i++){
        __half a = (i==0)? L : __high2half(m.h[i-1]);
        __half b = (i==7)? R : __low2half(m.h[i+1]);
        __half2 sl = __halves2half2(a, __low2half(m.h[i]));
        __half2 sr = __halves2half2(__high2half(m.h[i]), b);
        o.h[i] = __hmin2(__hmin2(sl, m.h[i]), sr);
    }
    return o;
}
__device__ __forceinline__ Row hmax3_row(const Row& m, int lane){
    unsigned up = __shfl_up_sync(FULLM, h2u(m.h[7]), 1);
    unsigned dn = __shfl_down_sync(FULLM, h2u(m.h[0]), 1);
    __half L = (lane==0)  ? __low2half(m.h[0])  : __high2half(u2h(up));
    __half R = (lane==31) ? __high2half(m.h[7]) : __low2half(u2h(dn));
    Row o;
    #pragma unroll
    for (int i=0;i<8;i++){
        __half a = (i==0)? L : __high2half(m.h[i-1]);
        __half b = (i==7)? R : __low2half(m.h[i+1]);
        __half2 sl = __halves2half2(a, __low2half(m.h[i]));
        __half2 sr = __halves2half2(__high2half(m.h[i]), b);
        o.h[i] = __hmax2(__hmax2(sl, m.h[i]), sr);
    }
    return o;
}

// erode = min(min(up,dn), hmin3(md))  (center md already inside hmin3)
__device__ __forceinline__ Row erode_row(const Row& up, const Row& md, const Row& dn, int lane){
    Row h = hmin3_row(md, lane);
    Row o;
    #pragma unroll
    for (int i=0;i<8;i++)
        o.h[i] = __hmin2(__hmin2(up.h[i], dn.h[i]), h.h[i]);
    return o;
}
// dilate = 3x3 max, separable
__device__ __forceinline__ Row dilate_rows(const Row& a, const Row& b, const Row& c, int lane){
    Row v;
    #pragma unroll
    for (int i=0;i<8;i++) v.h[i] = __hmax2(__hmax2(a.h[i], b.h[i]), c.h[i]);
    return hmax3_row(v, lane);
}

// ---------------------------------------------------------------------------
__global__ void prep_kernel(const float* __restrict__ pred, const float* __restrict__ tgt) {
    int i = blockIdx.x * blockDim.x + threadIdx.x;
    int stride = gridDim.x * blockDim.x;
    const float4* p4 = (const float4*)pred;
    const float4* t4 = (const float4*)tgt;
    for (; i < NTOT/4; i += stride) {
        float4 p = p4[i];
        p.x = 1.f/(1.f+__expf(-p.x)); p.y = 1.f/(1.f+__expf(-p.y));
        p.z = 1.f/(1.f+__expf(-p.z)); p.w = 1.f/(1.f+__expf(-p.w));
        uint2 hp;
        hp.x = h2u(__floats2half2_rn(p.x, p.y));
        hp.y = h2u(__floats2half2_rn(p.z, p.w));
        *(uint2*)&g_h0[(size_t)4*i] = hp;
        float4 t = t4[i];
        uint2 ht;
        ht.x = h2u(__floats2half2_rn(t.x, t.y));
        ht.y = h2u(__floats2half2_rn(t.z, t.w));
        *(uint2*)&g_h0[(size_t)NTOT + 4*i] = ht;
    }
}

// ---------------------------------------------------------------------------
// pair_iter: two fused skeleton stages, register rolling pipeline, software
// pipelined X loads. po load hoisted to iteration TOP (same-iteration, ~150
// instruction distance); d1/ta computed before e1n so e1_m1 dies early.
//   e1 = erode(X); delta_a = relu(X - dilate(e1))
//   e2 = erode(e1); delta_b = relu(e1 - dilate(e2))
//   P[y] = (first ? 1 : P[y]) * (1-delta_a)*(1-delta_b)   [all fp16 math]
//   Eout[y] = e2[y]
// ---------------------------------------------------------------------------
__global__ void __launch_bounds__(128, 4)
pair_iter(const __half* __restrict__ Xin, __half* __restrict__ P,
          __half* __restrict__ Eout, int first)
{
    const int w     = blockIdx.x * 4 + (threadIdx.x >> 5);
    const int lane  = threadIdx.x & 31;
    const int image = w >> 6;              // 0..63
    const int y0    = (w & 63) << 3;       // 8-row stripe start
    const int xoff  = lane * 16;

    const __half* ptrX = Xin + (size_t)image * IMG;
    __half*       ptrP = P   + (size_t)image * IMG;
    __half*       ptrE = Eout+ (size_t)image * IMG;

    const __half2 ONE2 = __floats2half2_rn(1.f, 1.f);
    const __half2 ZERO2 = __floats2half2_rn(0.f, 0.f);

    // ---- prologue: X rows y0-3 .. y0+3 ----
    Row x_m3 = ld_row(ptrX, y0-3, xoff);
    Row x_m2 = ld_row(ptrX, y0-2, xoff);
    Row x_m1 = ld_row(ptrX, y0-1, xoff);
    Row XA   = ld_row(ptrX, y0  , xoff);   // X@y
    Row XB   = ld_row(ptrX, y0+1, xoff);   // X@y+1
    Row XC   = ld_row(ptrX, y0+2, xoff);   // X@y+2
    Row XD   = ld_row(ptrX, y0+3, xoff);   // X@y+3 (pipelined)

    Row e1_0  = erode_row(x_m1, XA, XB, lane);          // e1@y0
    Row e1_p1 = erode_row(XA, XB, XC, lane);            // e1@y0+1
    Row e1_m1, e1_m2;
    if (y0 == 0) { e1_m1 = e1_0; e1_m2 = e1_0; }
    else {
        e1_m1 = erode_row(x_m2, x_m1, XA, lane);        // e1@y0-1
        e1_m2 = erode_row(x_m3, x_m2, x_m1, lane);      // e1@y0-2
    }
    Row e2_0 = erode_row(e1_m1, e1_0, e1_p1, lane);     // e2@y0
    Row e2_m1;
    if (y0 == 0) e2_m1 = e2_0;
    else         e2_m1 = erode_row(e1_m2, e1_m1, e1_0, lane);

    #pragma unroll
    for (int k = 0; k < 8; ++k) {
        const int y = y0 + k;
        // long-latency loads issued first, consumed late / next iteration
        Row Xnext = ld_row(ptrX, y+4, xoff);
        Row po;
        if (!first) po = ld_row(ptrP, y, xoff);

        // d1/ta first: e1_m1 dies here, before e1n is live
        Row d1 = dilate_rows(e1_m1, e1_0, e1_p1, lane);
        Row ta;
        #pragma unroll
        for (int i = 0; i < 8; i++)
            ta.h[i] = __hsub2(ONE2, __hmax2(__hsub2(XA.h[i], d1.h[i]), ZERO2));

        Row e1n, e2n;
        if (y+2 <= HW-1) e1n = erode_row(XB, XC, XD, lane);        else e1n = e1_p1;
        if (y+1 <= HW-1) e2n = erode_row(e1_0, e1_p1, e1n, lane);  else e2n = e2_0;

        Row d2 = dilate_rows(e2_m1, e2_0, e2n, lane);

        Row pv;
        #pragma unroll
        for (int i = 0; i < 8; i++) {
            __half2 tb = __hsub2(ONE2, __hmax2(__hsub2(e1_0.h[i], d2.h[i]), ZERO2));
            pv.h[i] = __hmul2(ta.h[i], tb);
        }
        if (!first) {
            #pragma unroll
            for (int i = 0; i < 8; i++) pv.h[i] = __hmul2(pv.h[i], po.h[i]);
        }
        st_row(ptrP, y, xoff, pv);
        st_row(ptrE, y, xoff, e2_0);

        // rotate windows
        XA = XB; XB = XC; XC = XD; XD = Xnext;
        e1_m1 = e1_0; e1_0 = e1_p1; e1_p1 = e1n;
        e2_m1 = e2_0; e2_0 = e2n;
    }
}

// ---------------------------------------------------------------------------
// final_iter: last stage (delta_10) + skel + per-warp reduction.
// po/ov loads hoisted to iteration top (same-iteration prefetch).
//   skel[y] = 1 - P[y]*(1 - relu(X[y]-dilate(erode(X))[y]))
//   a0 = sum(skel); a1 = sum(skel * other-stream h0)
// ---------------------------------------------------------------------------
__global__ void __launch_bounds__(128, 4)
final_iter(const __half* __restrict__ Xin, const __half* __restrict__ P,
           const __half* __restrict__ H0)
{
    const int w     = blockIdx.x * 4 + (threadIdx.x >> 5);
    const int lane  = threadIdx.x & 31;
    const int image = w >> 6;
    const int y0    = (w & 63) << 3;
    const int xoff  = lane * 16;

    const __half* ptrX = Xin + (size_t)image * IMG;
    const __half* ptrP = P   + (size_t)image * IMG;
    const __half* ptrO = H0  + (size_t)(image ^ 32) * IMG;   // opposite stream

    const __half2 ONE2 = __floats2half2_rn(1.f, 1.f);
    const __half2 ZERO2 = __floats2half2_rn(0.f, 0.f);

    Row x_m2 = ld_row(ptrX, y0-2, xoff);
    Row x_m1 = ld_row(ptrX, y0-1, xoff);
    Row XA   = ld_row(ptrX, y0,   xoff);   // X@y
    Row XB   = ld_row(ptrX, y0+1, xoff);   // X@y+1
    Row XC   = ld_row(ptrX, y0+2, xoff);   // X@y+2 (pipelined)

    Row e_0 = erode_row(x_m1, XA, XB, lane);             // e@y0
    Row e_m1;
    if (y0 == 0) e_m1 = e_0;
    else         e_m1 = erode_row(x_m2, x_m1, XA, lane); // e@y0-1

    double a0 = 0.0, a1 = 0.0;

    #pragma unroll
    for (int k = 0; k < 8; ++k) {
        const int y = y0 + k;
        // long-latency loads first
        Row Xnext = ld_row(ptrX, y+3, xoff);   // consumed next iteration
        Row po = ld_row(ptrP, y, xoff);
        Row ov = ld_row(ptrO, y, xoff);

        Row e_p1;
        if (y+1 <= HW-1) e_p1 = erode_row(XA, XB, XC, lane); else e_p1 = e_0;
        Row d = dilate_rows(e_m1, e_0, e_p1, lane);

        float s0 = 0.f, s1 = 0.f;
        #pragma unroll
        for (int i = 0; i < 8; i++) {
            // skel = 1 - P*(1-delta), delta = relu(X-d)  [half2 then widen]
            __half2 t  = __hsub2(ONE2, __hmax2(__hsub2(XA.h[i], d.h[i]), ZERO2));
            __half2 sk = __hsub2(ONE2, __hmul2(po.h[i], t));
            float2 skf = __half22float2(sk);
            float2 of  = __half22float2(ov.h[i]);
            s0 += skf.x + skf.y;
            s1 += skf.x*of.x + skf.y*of.y;
        }
        a0 += (double)s0;
        a1 += (double)s1;

        XA = XB; XB = XC; XC = Xnext;
        e_m1 = e_0; e_0 = e_p1;
    }

    // warp reduction (deterministic)
    #pragma unroll
    for (int off = 16; off; off >>= 1) {
        a0 += __shfl_xor_sync(FULLM, a0, off);
        a1 += __shfl_xor_sync(FULLM, a1, off);
    }
    if (lane == 0) {
        g_part[w*2 + 0] = a0;
        g_part[w*2 + 1] = a1;
    }
}

// ---------------------------------------------------------------------------
__global__ void final_sum(float* __restrict__ out)
{
    __shared__ double sh[4][256];
    int t = threadIdx.x;
    double a[4] = {0, 0, 0, 0};
    for (int i = t; i < NWARP; i += 256) {
        int s = (i >> 11) & 1;       // image = i>>6; s = image>>5
        a[2*s + 0] += g_part[i*2 + 0];
        a[2*s + 1] += g_part[i*2 + 1];
    }
    for (int k = 0; k < 4; k++) sh[k][t] = a[k];
    __syncthreads();
    for (int off = 128; off; off >>= 1) {
        if (t < off)
            for (int k = 0; k < 4; k++) sh[k][t] += sh[k][t + off];
        __syncthreads();
    }
    if (t == 0) {
        // s=0: pred-skel sums (sum skel, sum skel*target)
        // s=1: target-skel sums (sum skel, sum skel*prob)
        double tprec = (sh[1][0] + 1.0) / (sh[0][0] + 1.0);
        double tsens = (sh[3][0] + 1.0) / (sh[2][0] + 1.0);
        double cl = 2.0 * tprec * tsens / (tprec + tsens + 1e-7);
        out[0] = (float)(1.0 - cl);
    }
}

// ---------------------------------------------------------------------------
extern "C" void kernel_launch(void* const* d_in, const int* in_sizes, int n_in,
                              void* d_out, int out_size)
{
    const float* pred = (const float*)d_in[0];
    const float* tgt  = (const float*)d_in[1];

    __half *h0, *eA, *eB, *P;
    cudaGetSymbolAddress((void**)&h0, g_h0);
    cudaGetSymbolAddress((void**)&eA, g_eA);
    cudaGetSymbolAddress((void**)&eB, g_eB);
    cudaGetSymbolAddress((void**)&P,  g_P);

    prep_kernel<<<2048, 256>>>(pred, tgt);

    dim3 grid(NWARP/4);   // 1024 blocks, 4 warps each
    dim3 blk(128);

    pair_iter<<<grid, blk>>>(h0, P, eA, 1);   // d0,d1 ; out e2
    pair_iter<<<grid, blk>>>(eA, P, eB, 0);   // d2,d3 ; out e4
    pair_iter<<<grid, blk>>>(eB, P, eA, 0);   // d4,d5 ; out e6
    pair_iter<<<grid, blk>>>(eA, P, eB, 0);   // d6,d7 ; out e8
    pair_iter<<<grid, blk>>>(eB, P, eA, 0);   // d8,d9 ; out e10
    final_iter<<<grid, blk>>>(eA, P, h0);     // d10 + skel + reduction
    final_sum<<<1, 256>>>((float*)d_out);
}

// round 17
// speedup vs baseline: 1.4213x; 1.4213x over previous
#include <cuda_runtime.h>
#include <cuda_fp16.h>

#define HW    512
#define IMG   (HW*HW)
#define BATCH 32
#define NTOT  (BATCH*IMG)        // per stream
#define NWARP 4096               // 64 images * 64 stripes of 8 rows
#define FULLM 0xffffffffu

// __device__ scratch (no allocation allowed)
__device__ __align__(16) __half g_h0[2*NTOT];   // image i = s*32+b
__device__ __align__(16) __half g_eA[2*NTOT];
__device__ __align__(16) __half g_eB[2*NTOT];
__device__ __align__(16) __half g_P [2*NTOT];   // running product (1-skel), fp16
__device__ double g_part[NWARP*2];

__device__ __forceinline__ int clampi(int v){ return v<0?0:(v>HW-1?HW-1:v); }

struct Row { __half2 h[8]; };    // 16 halves: lane covers gx [16*lane, 16*lane+15]

__device__ __forceinline__ unsigned h2u(__half2 x){ return *reinterpret_cast<unsigned*>(&x); }
__device__ __forceinline__ __half2  u2h(unsigned x){ return *reinterpret_cast<__half2*>(&x); }

__device__ __forceinline__ Row ld_row(const __half* base, int y, int xoff){
    const uint4* p = reinterpret_cast<const uint4*>(base + (size_t)clampi(y)*HW + xoff);
    uint4 a = p[0], b = p[1];
    Row r;
    r.h[0]=u2h(a.x); r.h[1]=u2h(a.y); r.h[2]=u2h(a.z); r.h[3]=u2h(a.w);
    r.h[4]=u2h(b.x); r.h[5]=u2h(b.y); r.h[6]=u2h(b.z); r.h[7]=u2h(b.w);
    return r;
}
__device__ __forceinline__ void st_row(__half* base, int y, int xoff, const Row& r){
    uint4 a, b;
    a.x=h2u(r.h[0]); a.y=h2u(r.h[1]); a.z=h2u(r.h[2]); a.w=h2u(r.h[3]);
    b.x=h2u(r.h[4]); b.y=h2u(r.h[5]); b.z=h2u(r.h[6]); b.w=h2u(r.h[7]);
    uint4* p = reinterpret_cast<uint4*>(base + (size_t)y*HW + xoff);
    p[0]=a; p[1]=b;
}

// horizontal 3-min over the 512-wide row; lane-boundary halves via shuffle;
// image x-edges use duplicated edge element (== SAME pad identity for min).
__device__ __forceinline__ Row hmin3_row(const Row& m, int lane){
    unsigned up = __shfl_up_sync(FULLM, h2u(m.h[7]), 1);
    unsigned dn = __shfl_down_sync(FULLM, h2u(m.h[0]), 1);
    __half L = (lane==0)  ? __low2half(m.h[0])  : __high2half(u2h(up));
    __half R = (lane==31) ? __high2half(m.h[7]) : __low2half(u2h(dn));
    Row o;
    #pragma unroll
    for (int i=0;i<8;i++){
        __half a = (i==0)? L : __high2half(m.h[i-1]);
        __half b = (i==7)? R : __low2half(m.h[i+1]);
        __half2 sl = __halves2half2(a, __low2half(m.h[i]));
        __half2 sr = __halves2half2(__high2half(m.h[i]), b);
        o.h[i] = __hmin2(__hmin2(sl, m.h[i]), sr);
    }
    return o;
}
__device__ __forceinline__ Row hmax3_row(const Row& m, int lane){
    unsigned up = __shfl_up_sync(FULLM, h2u(m.h[7]), 1);
    unsigned dn = __shfl_down_sync(FULLM, h2u(m.h[0]), 1);
    __half L = (lane==0)  ? __low2half(m.h[0])  : __high2half(u2h(up));
    __half R = (lane==31) ? __high2half(m.h[7]) : __low2half(u2h(dn));
    Row o;
    #pragma unroll
    for (int i=0;i<8;i++){
        __half a = (i==0)? L : __high2half(m.h[i-1]);
        __half b = (i==7)? R : __low2half(m.h[i+1]);
        __half2 sl = __halves2half2(a, __low2half(m.h[i]));
        __half2 sr = __halves2half2(__high2half(m.h[i]), b);
        o.h[i] = __hmax2(__hmax2(sl, m.h[i]), sr);
    }
    return o;
}

// erode = min(min(up,dn), hmin3(md)) — center md already inside hmin3(md),
// so the extra min against md is dropped (bit-exact, 8 fewer HMNMX2).
__device__ __forceinline__ Row erode_row(const Row& up, const Row& md, const Row& dn, int lane){
    Row h = hmin3_row(md, lane);
    Row o;
    #pragma unroll
    for (int i=0;i<8;i++)
        o.h[i] = __hmin2(__hmin2(up.h[i], dn.h[i]), h.h[i]);
    return o;
}
// dilate = 3x3 max, separable
__device__ __forceinline__ Row dilate_rows(const Row& a, const Row& b, const Row& c, int lane){
    Row v;
    #pragma unroll
    for (int i=0;i<8;i++) v.h[i] = __hmax2(__hmax2(a.h[i], b.h[i]), c.h[i]);
    return hmax3_row(v, lane);
}

// ---------------------------------------------------------------------------
__global__ void prep_kernel(const float* __restrict__ pred, const float* __restrict__ tgt) {
    int i = blockIdx.x * blockDim.x + threadIdx.x;
    int stride = gridDim.x * blockDim.x;
    const float4* p4 = (const float4*)pred;
    const float4* t4 = (const float4*)tgt;
    for (; i < NTOT/4; i += stride) {
        float4 p = p4[i];
        p.x = 1.f/(1.f+__expf(-p.x)); p.y = 1.f/(1.f+__expf(-p.y));
        p.z = 1.f/(1.f+__expf(-p.z)); p.w = 1.f/(1.f+__expf(-p.w));
        uint2 hp;
        hp.x = h2u(__floats2half2_rn(p.x, p.y));
        hp.y = h2u(__floats2half2_rn(p.z, p.w));
        *(uint2*)&g_h0[(size_t)4*i] = hp;
        float4 t = t4[i];
        uint2 ht;
        ht.x = h2u(__floats2half2_rn(t.x, t.y));
        ht.y = h2u(__floats2half2_rn(t.z, t.w));
        *(uint2*)&g_h0[(size_t)NTOT + 4*i] = ht;
    }
}

// ---------------------------------------------------------------------------
// pair_iter: two fused skeleton stages, register rolling pipeline, software
// pipelined X loads (4-deep window; fresh load consumed only next iteration).
// P load stays in-iteration at its R9 position: hoisting it spills (R10/R15).
//   e1 = erode(X); delta_a = relu(X - dilate(e1))
//   e2 = erode(e1); delta_b = relu(e1 - dilate(e2))
//   P[y] = (first ? 1 : P[y]) * (1-delta_a)*(1-delta_b)   [all fp16 math]
//   Eout[y] = e2[y]
// ---------------------------------------------------------------------------
__global__ void __launch_bounds__(128, 4)
pair_iter(const __half* __restrict__ Xin, __half* __restrict__ P,
          __half* __restrict__ Eout, int first)
{
    const int w     = blockIdx.x * 4 + (threadIdx.x >> 5);
    const int lane  = threadIdx.x & 31;
    const int image = w >> 6;              // 0..63
    const int y0    = (w & 63) << 3;       // 8-row stripe start
    const int xoff  = lane * 16;

    const __half* ptrX = Xin + (size_t)image * IMG;
    __half*       ptrP = P   + (size_t)image * IMG;
    __half*       ptrE = Eout+ (size_t)image * IMG;

    const __half2 ONE2 = __floats2half2_rn(1.f, 1.f);
    const __half2 ZERO2 = __floats2half2_rn(0.f, 0.f);

    // ---- prologue: X rows y0-3 .. y0+3 ----
    Row x_m3 = ld_row(ptrX, y0-3, xoff);
    Row x_m2 = ld_row(ptrX, y0-2, xoff);
    Row x_m1 = ld_row(ptrX, y0-1, xoff);
    Row XA   = ld_row(ptrX, y0  , xoff);   // X@y
    Row XB   = ld_row(ptrX, y0+1, xoff);   // X@y+1
    Row XC   = ld_row(ptrX, y0+2, xoff);   // X@y+2
    Row XD   = ld_row(ptrX, y0+3, xoff);   // X@y+3 (pipelined)

    Row e1_0  = erode_row(x_m1, XA, XB, lane);          // e1@y0
    Row e1_p1 = erode_row(XA, XB, XC, lane);            // e1@y0+1
    Row e1_m1, e1_m2;
    if (y0 == 0) { e1_m1 = e1_0; e1_m2 = e1_0; }
    else {
        e1_m1 = erode_row(x_m2, x_m1, XA, lane);        // e1@y0-1
        e1_m2 = erode_row(x_m3, x_m2, x_m1, lane);      // e1@y0-2
    }
    Row e2_0 = erode_row(e1_m1, e1_0, e1_p1, lane);     // e2@y0
    Row e2_m1;
    if (y0 == 0) e2_m1 = e2_0;
    else         e2_m1 = erode_row(e1_m2, e1_m1, e1_0, lane);

    #pragma unroll
    for (int k = 0; k < 8; ++k) {
        const int y = y0 + k;
        // issue next X load early; consumed only next iteration
        Row Xnext = ld_row(ptrX, y+4, xoff);

        Row e1n, e2n;
        if (y+2 <= HW-1) e1n = erode_row(XB, XC, XD, lane);        else e1n = e1_p1;
        if (y+1 <= HW-1) e2n = erode_row(e1_0, e1_p1, e1n, lane);  else e2n = e2_0;

        Row d1 = dilate_rows(e1_m1, e1_0, e1_p1, lane);
        Row d2 = dilate_rows(e2_m1, e2_0, e2n, lane);

        // P update entirely in half2: pv = (1-relu(X-d1)) * (1-relu(e1-d2)) [* Pold]
        Row pv;
        #pragma unroll
        for (int i = 0; i < 8; i++) {
            __half2 ta = __hsub2(ONE2, __hmax2(__hsub2(XA.h[i],   d1.h[i]), ZERO2));
            __half2 tb = __hsub2(ONE2, __hmax2(__hsub2(e1_0.h[i], d2.h[i]), ZERO2));
            pv.h[i] = __hmul2(ta, tb);
        }
        if (!first) {
            Row po = ld_row(ptrP, y, xoff);
            #pragma unroll
            for (int i = 0; i < 8; i++) pv.h[i] = __hmul2(pv.h[i], po.h[i]);
        }
        st_row(ptrP, y, xoff, pv);
        st_row(ptrE, y, xoff, e2_0);

        // rotate windows
        XA = XB; XB = XC; XC = XD; XD = Xnext;
        e1_m1 = e1_0; e1_0 = e1_p1; e1_p1 = e1n;
        e2_m1 = e2_0; e2_0 = e2n;
    }
}

// ---------------------------------------------------------------------------
// final_iter: last stage (delta_10) + skel + per-warp reduction.
//   skel[y] = 1 - P[y]*(1 - relu(X[y]-dilate(erode(X))[y]))
//   a0 = sum(skel); a1 = sum(skel * other-stream h0)
// ---------------------------------------------------------------------------
__global__ void __launch_bounds__(128, 4)
final_iter(const __half* __restrict__ Xin, const __half* __restrict__ P,
           const __half* __restrict__ H0)
{
    const int w     = blockIdx.x * 4 + (threadIdx.x >> 5);
    const int lane  = threadIdx.x & 31;
    const int image = w >> 6;
    const int y0    = (w & 63) << 3;
    const int xoff  = lane * 16;

    const __half* ptrX = Xin + (size_t)image * IMG;
    const __half* ptrP = P   + (size_t)image * IMG;
    const __half* ptrO = H0  + (size_t)(image ^ 32) * IMG;   // opposite stream

    const __half2 ONE2 = __floats2half2_rn(1.f, 1.f);
    const __half2 ZERO2 = __floats2half2_rn(0.f, 0.f);

    Row x_m2 = ld_row(ptrX, y0-2, xoff);
    Row x_m1 = ld_row(ptrX, y0-1, xoff);
    Row XA   = ld_row(ptrX, y0,   xoff);   // X@y
    Row XB   = ld_row(ptrX, y0+1, xoff);   // X@y+1
    Row XC   = ld_row(ptrX, y0+2, xoff);   // X@y+2 (pipelined)

    Row e_0 = erode_row(x_m1, XA, XB, lane);             // e@y0
    Row e_m1;
    if (y0 == 0) e_m1 = e_0;
    else         e_m1 = erode_row(x_m2, x_m1, XA, lane); // e@y0-1

    double a0 = 0.0, a1 = 0.0;

    #pragma unroll
    for (int k = 0; k < 8; ++k) {
        const int y = y0 + k;
        Row Xnext = ld_row(ptrX, y+3, xoff);   // consumed next iteration

        Row e_p1;
        if (y+1 <= HW-1) e_p1 = erode_row(XA, XB, XC, lane); else e_p1 = e_0;
        Row d = dilate_rows(e_m1, e_0, e_p1, lane);

        Row po = ld_row(ptrP, y, xoff);
        Row ov = ld_row(ptrO, y, xoff);

        float s0 = 0.f, s1 = 0.f;
        #pragma unroll
        for (int i = 0; i < 8; i++) {
            // skel = 1 - P*(1-delta), delta = relu(X-d)  [half2 then widen]
            __half2 t  = __hsub2(ONE2, __hmax2(__hsub2(XA.h[i], d.h[i]), ZERO2));
            __half2 sk = __hsub2(ONE2, __hmul2(po.h[i], t));
            float2 skf = __half22float2(sk);
            float2 of  = __half22float2(ov.h[i]);
            s0 += skf.x + skf.y;
            s1 += skf.x*of.x + skf.y*of.y;
        }
        a0 += (double)s0;
        a1 += (double)s1;

        XA = XB; XB = XC; XC = Xnext;
        e_m1 = e_0; e_0 = e_p1;
    }

    // warp reduction (deterministic)
    #pragma unroll
    for (int off = 16; off; off >>= 1) {
        a0 += __shfl_xor_sync(FULLM, a0, off);
        a1 += __shfl_xor_sync(FULLM, a1, off);
    }
    if (lane == 0) {
        g_part[w*2 + 0] = a0;
        g_part[w*2 + 1] = a1;
    }
}

// ---------------------------------------------------------------------------
__global__ void final_sum(float* __restrict__ out)
{
    __shared__ double sh[4][256];
    int t = threadIdx.x;
    double a[4] = {0, 0, 0, 0};
    for (int i = t; i < NWARP; i += 256) {
        int s = (i >> 11) & 1;       // image = i>>6; s = image>>5
        a[2*s + 0] += g_part[i*2 + 0];
        a[2*s + 1] += g_part[i*2 + 1];
    }
    for (int k = 0; k < 4; k++) sh[k][t] = a[k];
    __syncthreads();
    for (int off = 128; off; off >>= 1) {
        if (t < off)
            for (int k = 0; k < 4; k++) sh[k][t] += sh[k][t + off];
        __syncthreads();
    }
    if (t == 0) {
        // s=0: pred-skel sums (sum skel, sum skel*target)
        // s=1: target-skel sums (sum skel, sum skel*prob)
        double tprec = (sh[1][0] + 1.0) / (sh[0][0] + 1.0);
        double tsens = (sh[3][0] + 1.0) / (sh[2][0] + 1.0);
        double cl = 2.0 * tprec * tsens / (tprec + tsens + 1e-7);
        out[0] = (float)(1.0 - cl);
    }
}

// ---------------------------------------------------------------------------
extern "C" void kernel_launch(void* const* d_in, const int* in_sizes, int n_in,
                              void* d_out, int out_size)
{
    const float* pred = (const float*)d_in[0];
    const float* tgt  = (const float*)d_in[1];

    __half *h0, *eA, *eB, *P;
    cudaGetSymbolAddress((void**)&h0, g_h0);
    cudaGetSymbolAddress((void**)&eA, g_eA);
    cudaGetSymbolAddress((void**)&eB, g_eB);
    cudaGetSymbolAddress((void**)&P,  g_P);

    prep_kernel<<<2048, 256>>>(pred, tgt);

    dim3 grid(NWARP/4);   // 1024 blocks, 4 warps each
    dim3 blk(128);

    pair_iter<<<grid, blk>>>(h0, P, eA, 1);   // d0,d1 ; out e2
    pair_iter<<<grid, blk>>>(eA, P, eB, 0);   // d2,d3 ; out e4
    pair_iter<<<grid, blk>>>(eB, P, eA, 0);   // d4,d5 ; out e6
    pair_iter<<<grid, blk>>>(eA, P, eB, 0);   // d6,d7 ; out e8
    pair_iter<<<grid, blk>>>(eB, P, eA, 0);   // d8,d9 ; out e10
    final_iter<<<grid, blk>>>(eA, P, h0);     // d10 + skel + reduction
    final_sum<<<1, 256>>>((float*)d_out);
}